// round 16
// baseline (speedup 1.0000x reference)
#include <cuda_runtime.h>
#include <math.h>

// Split-KV (flash-decoding) stage-2 merge. B=256, H=32, S=16, D=128, fp32.
//
// R15 = R12/R14 body (two 8-deep register rounds; R14 proved the SASS
// schedule is already optimal -- identical 8.192us) with ONE change:
// __launch_bounds__(128, 12) forces the allocation from 47->~40 regs,
// moving the residency cap from 10 to 12 blocks/SM (40->48 warps, +20%
// concurrency at unchanged MLP 8). The warp-uniform scalars (nv, seq,
// splits) belong in the uniform register file; buffers+acc+ptrs audit to
// ~43 live GPRs, so no spill expected.
// Kept: 1 warp/head, shfl-held weights, exact per-load predication,
// cycle-0 LSE/s0/s1 issue, float ceil-divs (exact for seq<=8192,
// splits<=16), half-warp reductions, 128-thread blocks.

#define B_DIM 256
#define H_DIM 32
#define LOG2E 1.4426950408889634f

__global__ __launch_bounds__(128, 12)
void splitkv_merge_kernel(const float* __restrict__ att_out,
                          const float* __restrict__ att_lse,
                          const int*   __restrict__ kv_indptr,
                          const int*   __restrict__ num_kv_splits,
                          float*       __restrict__ out)
{
    const unsigned hid  = (blockIdx.x * 128u + threadIdx.x) >> 5;   // (b,h)
    const unsigned lane = threadIdx.x & 31u;
    const unsigned b    = hid >> 5;                                 // H == 32

    const float4* __restrict__ src =
        reinterpret_cast<const float4*>(att_out) + hid * 512u + lane;

    // ---- cycle-0 issue group (independent of the geometry chain) ----
    float4 v0 = src[0 * 32];                    // s=0: always valid
    float4 v1 = src[1 * 32];                    // s=1: w=0 kills it if nv==1

    float lse = -INFINITY;
    if (lane < 16u)
        lse = att_lse[hid * 16u + lane];

    const int ip0 = kv_indptr[b];
    const int ip1 = kv_indptr[b + 1];
    const unsigned splits = (unsigned)num_kv_splits[b];

    // ---- geometry via exact float ceil-divs (seq<=8192, splits<=16) ----
    const unsigned seq = (unsigned)(ip1 - ip0);
    const float fseq = __uint2float_rn(seq);
    const unsigned c1 = (unsigned)ceilf(fseq / __uint2float_rn(splits));
    const unsigned per_split = (c1 + 31u) & ~31u;
    const unsigned nv =
        (unsigned)ceilf(fseq / __uint2float_rn(per_split));   // 1..16 prefix

    // ---- round 1 remainder: s=2..7, front-batched, predicated ----
    float4 v2, v3, v4, v5, v6, v7;
    v2 = v3 = v4 = v5 = v6 = v7 = make_float4(0.f, 0.f, 0.f, 0.f);
    if (2u < nv) {                              // warp-uniform skip
        v2 = src[2 * 32];
        if (3u < nv) v3 = src[3 * 32];
        if (4u < nv) v4 = src[4 * 32];
        if (5u < nv) v5 = src[5 * 32];
        if (6u < nv) v6 = src[6 * 32];
        if (7u < nv) v7 = src[7 * 32];
    }

    // ---- weights: 4-step low-half reductions + single broadcast ----
    if (lane >= nv) lse = -INFINITY;

    float m = lse;
    #pragma unroll
    for (int o = 8; o > 0; o >>= 1)
        m = fmaxf(m, __shfl_xor_sync(0xffffffffu, m, o));

    const float w = (lane < nv) ? exp2f((lse - m) * LOG2E) : 0.0f;

    float esum = w;
    #pragma unroll
    for (int o = 8; o > 0; o >>= 1)
        esum += __shfl_xor_sync(0xffffffffu, esum, o);

    const float inv_esum = __shfl_sync(0xffffffffu, 1.0f / esum, 0);

#define ACC(S, V)                                            \
    ws = __shfl_sync(0xffffffffu, w, S);                     \
    acc.x = fmaf(ws, V.x, acc.x);                            \
    acc.y = fmaf(ws, V.y, acc.y);                            \
    acc.z = fmaf(ws, V.z, acc.z);                            \
    acc.w = fmaf(ws, V.w, acc.w);

    // ---- consume s0..3, recycle v0..v3 for s8..11 ----
    float ws = __shfl_sync(0xffffffffu, w, 0);
    float4 acc;
    acc.x = ws * v0.x; acc.y = ws * v0.y;
    acc.z = ws * v0.z; acc.w = ws * v0.w;
    ACC(1, v1) ACC(2, v2) ACC(3, v3)

    if (8u < nv) {                              // issue s8..11 early
        v0 = src[8 * 32];
        v1 = v2 = v3 = make_float4(0.f, 0.f, 0.f, 0.f);
        if ( 9u < nv) v1 = src[ 9 * 32];
        if (10u < nv) v2 = src[10 * 32];
        if (11u < nv) v3 = src[11 * 32];
    }

    // ---- consume s4..7, recycle v4..v7 for s12..15 ----
    ACC(4, v4) ACC(5, v5) ACC(6, v6) ACC(7, v7)

    if (8u < nv) {
        v4 = v5 = v6 = v7 = make_float4(0.f, 0.f, 0.f, 0.f);
        if (12u < nv) v4 = src[12 * 32];
        if (13u < nv) v5 = src[13 * 32];
        if (14u < nv) v6 = src[14 * 32];
        if (15u < nv) v7 = src[15 * 32];

        ACC( 8, v0) ACC( 9, v1) ACC(10, v2) ACC(11, v3)
        ACC(12, v4) ACC(13, v5) ACC(14, v6) ACC(15, v7)
    }
#undef ACC

    acc.x *= inv_esum;
    acc.y *= inv_esum;
    acc.z *= inv_esum;
    acc.w *= inv_esum;

    reinterpret_cast<float4*>(out)[hid * 32u + lane] = acc;
}

extern "C" void kernel_launch(void* const* d_in, const int* in_sizes, int n_in,
                              void* d_out, int out_size)
{
    const float* att_out       = (const float*)d_in[0];
    const float* att_lse       = (const float*)d_in[1];
    // d_in[2] = q, d_in[3] = v_buffer : unused (shape-only in the reference)
    const int*   kv_indptr     = (const int*)d_in[4];
    const int*   num_kv_splits = (const int*)d_in[5];
    float*       out           = (float*)d_out;

    // 8192 head-warps, 4 warps per 128-thread block -> 2048 blocks exact
    splitkv_merge_kernel<<<(B_DIM * H_DIM) / 4, 128>>>(att_out, att_lse,
                                                       kv_indptr, num_kv_splits, out);
}

// round 17
// speedup vs baseline: 1.2109x; 1.2109x over previous
#include <cuda_runtime.h>
#include <math.h>

// Split-KV (flash-decoding) stage-2 merge. B=256, H=32, S=16, D=128, fp32.
//
// R16 = R12 verbatim (47 regs, 10 blocks/SM, two 8-deep rounds -- the
// proven 8.19us optimum; R15 showed forcing regs lower spills, R13 showed
// smem staging taxes the warm regime) + ONE register-free addition:
// prefetch.global.L1 for s=8..15 issued alongside the round-1 loads.
// Round-2 LDGs then hit L1 (~39cy) instead of L2 (~250cy warm), removing
// the last exposed latency for heavy warps. 8 lines x 512B x 40 warps =
// 160KB < 228KB L1. Worst case (prefetch ignored) == R12 exactly.
// Kept: 1 warp/head, shfl-held weights, exact per-load predication,
// cycle-0 LSE/s0/s1 issue, float ceil-divs (exact for seq<=8192,
// splits<=16), half-warp reductions, 128-thread blocks, NO forced
// launch-bounds occupancy (R15's spill lesson).

#define B_DIM 256
#define H_DIM 32
#define LOG2E 1.4426950408889634f

__global__ __launch_bounds__(128)
void splitkv_merge_kernel(const float* __restrict__ att_out,
                          const float* __restrict__ att_lse,
                          const int*   __restrict__ kv_indptr,
                          const int*   __restrict__ num_kv_splits,
                          float*       __restrict__ out)
{
    const unsigned hid  = (blockIdx.x * 128u + threadIdx.x) >> 5;   // (b,h)
    const unsigned lane = threadIdx.x & 31u;
    const unsigned b    = hid >> 5;                                 // H == 32

    const float4* __restrict__ src =
        reinterpret_cast<const float4*>(att_out) + hid * 512u + lane;

    // ---- cycle-0 issue group (independent of the geometry chain) ----
    float4 v0 = src[0 * 32];                    // s=0: always valid
    float4 v1 = src[1 * 32];                    // s=1: w=0 kills it if nv==1

    float lse = -INFINITY;
    if (lane < 16u)
        lse = att_lse[hid * 16u + lane];

    const int ip0 = kv_indptr[b];
    const int ip1 = kv_indptr[b + 1];
    const unsigned splits = (unsigned)num_kv_splits[b];

    // ---- geometry via exact float ceil-divs (seq<=8192, splits<=16) ----
    const unsigned seq = (unsigned)(ip1 - ip0);
    const float fseq = __uint2float_rn(seq);
    const unsigned c1 = (unsigned)ceilf(fseq / __uint2float_rn(splits));
    const unsigned per_split = (c1 + 31u) & ~31u;
    const unsigned nv =
        (unsigned)ceilf(fseq / __uint2float_rn(per_split));   // 1..16 prefix

    // ---- round 1 remainder: s=2..7, front-batched, predicated ----
    const float4 z = make_float4(0.f, 0.f, 0.f, 0.f);
    float4 v2 = z, v3 = z, v4 = z, v5 = z, v6 = z, v7 = z;
    if (2u < nv) {                              // warp-uniform skip
        v2 = src[2 * 32];
        if (3u < nv) v3 = src[3 * 32];
        if (4u < nv) v4 = src[4 * 32];
        if (5u < nv) v5 = src[5 * 32];
        if (6u < nv) v6 = src[6 * 32];
        if (7u < nv) v7 = src[7 * 32];
    }

    // ---- round 2 prefetch: L1-warm s=8..15 with ZERO register cost ----
    if (8u < nv) {
        asm volatile("prefetch.global.L1 [%0];" :: "l"((const void*)(src +  8 * 32)));
        if ( 9u < nv) asm volatile("prefetch.global.L1 [%0];" :: "l"((const void*)(src +  9 * 32)));
        if (10u < nv) asm volatile("prefetch.global.L1 [%0];" :: "l"((const void*)(src + 10 * 32)));
        if (11u < nv) asm volatile("prefetch.global.L1 [%0];" :: "l"((const void*)(src + 11 * 32)));
        if (12u < nv) asm volatile("prefetch.global.L1 [%0];" :: "l"((const void*)(src + 12 * 32)));
        if (13u < nv) asm volatile("prefetch.global.L1 [%0];" :: "l"((const void*)(src + 13 * 32)));
        if (14u < nv) asm volatile("prefetch.global.L1 [%0];" :: "l"((const void*)(src + 14 * 32)));
        if (15u < nv) asm volatile("prefetch.global.L1 [%0];" :: "l"((const void*)(src + 15 * 32)));
    }

    // ---- weights: 4-step low-half reductions + single broadcast ----
    if (lane >= nv) lse = -INFINITY;

    float m = lse;
    #pragma unroll
    for (int o = 8; o > 0; o >>= 1)
        m = fmaxf(m, __shfl_xor_sync(0xffffffffu, m, o));

    const float w = (lane < nv) ? exp2f((lse - m) * LOG2E) : 0.0f;

    float esum = w;
    #pragma unroll
    for (int o = 8; o > 0; o >>= 1)
        esum += __shfl_xor_sync(0xffffffffu, esum, o);

    const float inv_esum = __shfl_sync(0xffffffffu, 1.0f / esum, 0);

    // ---- consume round 1 (s=0..7): invalid rows have v=0 AND w=0 ----
    float ws = __shfl_sync(0xffffffffu, w, 0);
    float4 acc;
    acc.x = ws * v0.x; acc.y = ws * v0.y;
    acc.z = ws * v0.z; acc.w = ws * v0.w;

#define ACC(S, V)                                            \
    ws = __shfl_sync(0xffffffffu, w, S);                     \
    acc.x = fmaf(ws, V.x, acc.x);                            \
    acc.y = fmaf(ws, V.y, acc.y);                            \
    acc.z = fmaf(ws, V.z, acc.z);                            \
    acc.w = fmaf(ws, V.w, acc.w);

    ACC(1, v1) ACC(2, v2) ACC(3, v3) ACC(4, v4)
    ACC(5, v5) ACC(6, v6) ACC(7, v7)

    // ---- round 2 (s=8..15): reuse the same 8 buffers (now L1 hits) ----
    if (8u < nv) {                              // warp-uniform skip
        v0 = src[8 * 32];
        v1 = v2 = v3 = v4 = v5 = v6 = v7 = z;
        if ( 9u < nv) v1 = src[ 9 * 32];
        if (10u < nv) v2 = src[10 * 32];
        if (11u < nv) v3 = src[11 * 32];
        if (12u < nv) v4 = src[12 * 32];
        if (13u < nv) v5 = src[13 * 32];
        if (14u < nv) v6 = src[14 * 32];
        if (15u < nv) v7 = src[15 * 32];

        ACC( 8, v0) ACC( 9, v1) ACC(10, v2) ACC(11, v3)
        ACC(12, v4) ACC(13, v5) ACC(14, v6) ACC(15, v7)
    }
#undef ACC

    acc.x *= inv_esum;
    acc.y *= inv_esum;
    acc.z *= inv_esum;
    acc.w *= inv_esum;

    reinterpret_cast<float4*>(out)[hid * 32u + lane] = acc;
}

extern "C" void kernel_launch(void* const* d_in, const int* in_sizes, int n_in,
                              void* d_out, int out_size)
{
    const float* att_out       = (const float*)d_in[0];
    const float* att_lse       = (const float*)d_in[1];
    // d_in[2] = q, d_in[3] = v_buffer : unused (shape-only in the reference)
    const int*   kv_indptr     = (const int*)d_in[4];
    const int*   num_kv_splits = (const int*)d_in[5];
    float*       out           = (float*)d_out;

    // 8192 head-warps, 4 warps per 128-thread block -> 2048 blocks exact
    splitkv_merge_kernel<<<(B_DIM * H_DIM) / 4, 128>>>(att_out, att_lse,
                                                       kv_indptr, num_kv_splits, out);
}